// round 14
// baseline (speedup 1.0000x reference)
#include <cuda_runtime.h>
#include <cuda_bf16.h>
#include <cuda_fp16.h>
#include <math.h>
#include <stdint.h>

// Problem constants
#define NN 65536
#define DD 2048
#define LD 64          // d
#define SS 32          // s
#define KTRI 2080      // d*(d+1)/2
#define KTOT 96        // d + s

// Scratch: z^T n-major fp16, packed pairs: g_z[n*48 + kpair] (uint = half2). 12 MB.
__device__ unsigned g_z[(size_t)NN * 48];
// theta transposed to col-major fp16 pairs: g_theta_h[col*1040 + kpair]. 133 KB.
__device__ unsigned g_theta_h[32 * 1040];

// pack2h(lo, hi): uint with .lo = half(lo), .hi = half(hi)
__device__ __forceinline__ unsigned pack2h(float lo, float hi) {
    unsigned r;
    asm("cvt.rn.f16x2.f32 %0, %1, %2;" : "=r"(r) : "f"(hi), "f"(lo));
    return r;
}

__device__ __forceinline__ void mma_f16(float* c,
                                        unsigned a0, unsigned a1, unsigned a2, unsigned a3,
                                        unsigned b0, unsigned b1) {
    asm volatile(
        "mma.sync.aligned.m16n8k16.row.col.f32.f16.f16.f32 "
        "{%0,%1,%2,%3}, {%4,%5,%6,%7}, {%8,%9}, {%0,%1,%2,%3};"
        : "+f"(c[0]), "+f"(c[1]), "+f"(c[2]), "+f"(c[3])
        : "r"(a0), "r"(a1), "r"(a2), "r"(a3), "r"(b0), "r"(b1));
}

// ---------------------------------------------------------------------------
// Kernel 0: theta (2080 x 32 f32) -> g_theta_h (col-major half2 pairs)
// ---------------------------------------------------------------------------
__global__ void theta_half_kernel(const float* __restrict__ theta) {
    int idx = blockIdx.x * 256 + threadIdx.x;
    if (idx < 32 * 1040) {
        int col = idx / 1040, kp = idx % 1040;
        float lo = theta[(size_t)(2 * kp) * SS + col];
        float hi = theta[(size_t)(2 * kp + 1) * SS + col];
        g_theta_h[idx] = pack2h(lo, hi);
    }
}

// ---------------------------------------------------------------------------
// Kernel 1: quad^T (Ncols x 32) = psi^T (Ncols x 2080) @ theta (2080 x 32)
// psi generated on the fly from a phi tile in smem; fp16 MMA (m16n8k16).
// K1_COLS=256 but 512 THREADS / 16 warps (warp = 16 cols): smem unchanged
// (83.6KB -> 2 CTAs/SM) so warps/SMSP doubles 4 -> 8 for latency hiding.
// Writes g_z (n-major halves, R11 layout).
// ---------------------------------------------------------------------------
#define K1_COLS 256
#define PHI_STRIDE 264     // floats; conflict-free fragment reads
#define KC 208             // K chunk (2080 = 10 * 208) -> 13 k16-steps
#define TH_STRIDE 108      // uints per theta col (104 pairs + pad)

#define SMEM1_BYTES ((64 * PHI_STRIDE + 32 * TH_STRIDE) * 4 + 2 * KTRI)

__global__ __launch_bounds__(512)
void quad_kernel(const float* __restrict__ phi) {
    extern __shared__ float sm1[];
    float* phi_s    = sm1;                                  // 64 x 264 f32
    unsigned* th_s  = (unsigned*)(sm1 + 64 * PHI_STRIDE);   // 32 x 108 uints (half2)
    unsigned char* ii_s = (unsigned char*)(th_s + 32 * TH_STRIDE);
    unsigned char* jj_s = ii_s + KTRI;

    const int tid  = threadIdx.x;
    const int lane = tid & 31;
    const int wid  = tid >> 5;          // 0..15
    const int tig  = lane & 3;
    const int grp  = lane >> 2;
    const int c0   = blockIdx.x * K1_COLS;

    // Build (i,j) index tables for triu ordering
    for (int k = tid; k < KTRI; k += 512) {
        int gi = (int)(64.5f - sqrtf(64.5f * 64.5f - 2.0f * (float)k));
        gi = max(0, min(63, gi));
        while (gi > 0 && (gi * 64 - (gi * (gi - 1)) / 2) > k) --gi;
        while (gi < 63 && ((gi + 1) * 64 - ((gi + 1) * gi) / 2) <= k) ++gi;
        int base = gi * 64 - (gi * (gi - 1)) / 2;
        ii_s[k] = (unsigned char)gi;
        jj_s[k] = (unsigned char)(gi + (k - base));
    }

    // Load phi tile (64 x 256) f32
    for (int idx = tid; idx < 64 * (K1_COLS / 4); idx += 512) {
        int r  = idx / (K1_COLS / 4);
        int c4 = idx % (K1_COLS / 4);
        float4 v = *(const float4*)(phi + (size_t)r * NN + c0 + c4 * 4);
        float* dst = phi_s + r * PHI_STRIDE + c4 * 4;
        dst[0] = v.x; dst[1] = v.y; dst[2] = v.z; dst[3] = v.w;
    }
    __syncthreads();

    // phi rows of z: transpose from smem. 2 threads per n-col, 4 uint4 each.
    {
        int nl = tid & 255;
        int h  = tid >> 8;           // 0 or 1
        int n  = c0 + nl;
#pragma unroll
        for (int j = 0; j < 4; ++j) {
            int kp4 = h * 4 + j;     // uint4 index (0..7)
            uint4 v;
            unsigned* b = (unsigned*)&v;
#pragma unroll
            for (int jj = 0; jj < 4; ++jj) {
                int kp = kp4 * 4 + jj;
                b[jj] = pack2h(phi_s[(2 * kp) * PHI_STRIDE + nl],
                               phi_s[(2 * kp + 1) * PHI_STRIDE + nl]);
            }
            *(uint4*)(g_z + (size_t)n * 48 + kp4 * 4) = v;
        }
    }

    float acc[4][4];
#pragma unroll
    for (int b = 0; b < 4; b++)
#pragma unroll
        for (int q = 0; q < 4; q++) acc[b][q] = 0.f;

    const int wcol = wid * 16;

    for (int ch = 0; ch < KTRI / KC; ++ch) {
        const int kb = ch * KC;
        __syncthreads();  // protect th_s from previous chunk's readers
        // Stage theta chunk: 32 cols x 104 pairs
        for (int idx = tid; idx < 32 * 104; idx += 512) {
            int col = idx / 104, u = idx % 104;
            th_s[col * TH_STRIDE + u] = g_theta_h[col * 1040 + ch * 104 + u];
        }
        __syncthreads();

#pragma unroll 1
        for (int ks = 0; ks < 13; ++ks) {
            const int kg = kb + ks * 16 + 2 * tig;
            const float* pA = phi_s + ii_s[kg] * PHI_STRIDE;
            const float* qA = phi_s + jj_s[kg] * PHI_STRIDE;
            const float* pB = phi_s + ii_s[kg + 1] * PHI_STRIDE;
            const float* qB = phi_s + jj_s[kg + 1] * PHI_STRIDE;
            const float* pC = phi_s + ii_s[kg + 8] * PHI_STRIDE;
            const float* qC = phi_s + jj_s[kg + 8] * PHI_STRIDE;
            const float* pD = phi_s + ii_s[kg + 9] * PHI_STRIDE;
            const float* qD = phi_s + jj_s[kg + 9] * PHI_STRIDE;

            unsigned bfr[4][2];
#pragma unroll
            for (int nt = 0; nt < 4; ++nt) {
                int col = nt * 8 + grp;
                bfr[nt][0] = th_s[col * TH_STRIDE + ks * 8 + tig];
                bfr[nt][1] = th_s[col * TH_STRIDE + ks * 8 + tig + 4];
            }
            {
                int col = wcol + grp;
                unsigned a0 = pack2h(pA[col] * qA[col],         pB[col] * qB[col]);
                unsigned a1 = pack2h(pA[col + 8] * qA[col + 8], pB[col + 8] * qB[col + 8]);
                unsigned a2 = pack2h(pC[col] * qC[col],         pD[col] * qD[col]);
                unsigned a3 = pack2h(pC[col + 8] * qC[col + 8], pD[col + 8] * qD[col + 8]);
#pragma unroll
                for (int nt = 0; nt < 4; ++nt)
                    mma_f16(acc[nt], a0, a1, a2, a3, bfr[nt][0], bfr[nt][1]);
            }
        }
    }

    // Epilogue: quad rows of z (64..95), packed half2
    {
        int n = c0 + wcol + grp;
#pragma unroll
        for (int nt = 0; nt < 4; ++nt) {
            g_z[(size_t)n * 48       + 32 + nt * 4 + tig] = pack2h(acc[nt][0], acc[nt][1]);
            g_z[(size_t)(n + 8) * 48 + 32 + nt * 4 + tig] = pack2h(acc[nt][2], acc[nt][3]);
        }
    }
}

// ---------------------------------------------------------------------------
// Kernel 2 (R11 verbatim): out = c + Q @ z, fp16 MMA. Persistent CTA:
// 128 M x NT*128 N. 512 threads / 16 warps (32x32 warp tiles). TWO CTAs/SM:
//   regs <= 64 (launch_bounds(512,2)): A-frags reloaded per k-step from smem.
//   smem 110KB/CTA: Qs 26KB + 2x26KB B bufs + 32KB OUT buffer (2-pass epilogue).
// ---------------------------------------------------------------------------
#define NT 8
#define QSH 52                 // uints (half2 pairs) per Q row
#define BSH 52                 // uints per B row (48 data + pad); 208B, 16B-aligned
#define Q_OFF   0
#define B0_OFF  26624
#define B1_OFF  53248
#define OUT_OFF 79872          // 64 rows x 512B = 32KB
#define SMEM2_BYTES 112640

__device__ __forceinline__ void stage_B(char* Bdst, int n0g, int tid) {
#pragma unroll
    for (int i = 0; i < 3; ++i) {
        int idx = i * 512 + tid;          // 1536 = 128 n x 12 chunks
        int n = idx / 12, q = idx - n * 12;
        const unsigned* src = g_z + (size_t)(n0g + n) * 48 + q * 4;
        unsigned sa = (unsigned)__cvta_generic_to_shared(Bdst + n * (BSH * 4) + q * 16);
        asm volatile("cp.async.cg.shared.global [%0], [%1], 16;" :: "r"(sa), "l"(src));
    }
    asm volatile("cp.async.commit_group;" ::: "memory");
}

__global__ __launch_bounds__(512, 2)
void gemm_kernel(const float* __restrict__ cvec, const float* __restrict__ Q,
                 float* __restrict__ out) {
    extern __shared__ char sm2[];
    unsigned* Qs = (unsigned*)(sm2 + Q_OFF);   // persists across all tiles

    const int tid  = threadIdx.x;
    const int lane = tid & 31;
    const int wid  = tid >> 5;
    const int tig  = lane & 3;
    const int grp  = lane >> 2;
    const int wm   = wid & 3;   // 4 warps along M (32 rows)
    const int wn   = wid >> 2;  // 4 warps along N (32 cols)
    const int m0   = blockIdx.x * 128;         // 16 M-tiles (fast dim -> z L2 reuse)
    const int nb   = blockIdx.y * (128 * NT);  // 64 N-groups

    // Stage Q tile (128 x 96) as half2 pairs
    for (int idx = tid; idx < 128 * 48; idx += 512) {
        int m = idx / 48, hp = idx % 48;
        float2 v = *(const float2*)(Q + (size_t)(m0 + m) * KTOT + hp * 2);
        Qs[m * QSH + hp] = pack2h(v.x, v.y);
    }

    // Prefetch B tile 0
    stage_B(sm2 + B0_OFF, nb, tid);

    float cv[2][2];
#pragma unroll
    for (int mt = 0; mt < 2; ++mt) {
        cv[mt][0] = __ldg(cvec + m0 + wm * 32 + mt * 16 + grp);
        cv[mt][1] = __ldg(cvec + m0 + wm * 32 + mt * 16 + grp + 8);
    }

    __syncthreads();

    for (int t = 0; t < NT; ++t) {
        asm volatile("cp.async.wait_group 0;" ::: "memory");
        __syncthreads();   // B(t) ready; prior OUT-buffer reads complete

        if (t + 1 < NT)
            stage_B(sm2 + ((((t + 1) & 1) == 0) ? B0_OFF : B1_OFF), nb + (t + 1) * 128, tid);

        const unsigned* Bs = (const unsigned*)(sm2 + (((t & 1) == 0) ? B0_OFF : B1_OFF));
        const int n0 = nb + t * 128;

        float acc[2][4][4];
#pragma unroll
        for (int a = 0; a < 2; a++)
#pragma unroll
            for (int b = 0; b < 4; b++)
#pragma unroll
                for (int q = 0; q < 4; q++) acc[a][b][q] = 0.f;

#pragma unroll
        for (int ks = 0; ks < 6; ++ks) {
            // A fragments for this k-step (reloaded; conflict-free banks)
            unsigned afr[2][4];
#pragma unroll
            for (int mt = 0; mt < 2; ++mt) {
                int row = wm * 32 + mt * 16 + grp;
                afr[mt][0] = Qs[row * QSH + ks * 8 + tig];
                afr[mt][1] = Qs[(row + 8) * QSH + ks * 8 + tig];
                afr[mt][2] = Qs[row * QSH + ks * 8 + tig + 4];
                afr[mt][3] = Qs[(row + 8) * QSH + ks * 8 + tig + 4];
            }
#pragma unroll
            for (int nt = 0; nt < 4; ++nt) {
                int coln = wn * 32 + nt * 8 + grp;
                unsigned b0 = Bs[coln * BSH + ks * 8 + tig];
                unsigned b1 = Bs[coln * BSH + ks * 8 + tig + 4];
#pragma unroll
                for (int mt = 0; mt < 2; ++mt)
                    mma_f16(acc[mt][nt], afr[mt][0], afr[mt][1],
                            afr[mt][2], afr[mt][3], b0, b1);
            }
        }

        // ---- 2-pass epilogue through 32KB swizzled OUT buffer ----
        // Pass A: rows 0..63 (warps with wm<2 own them)
        if (wm < 2) {
#pragma unroll
            for (int mt = 0; mt < 2; ++mt) {
                int row = wm * 32 + mt * 16 + grp;       // 0..63; row&3 == grp&3
                int sw  = (grp & 3) << 2;
#pragma unroll
                for (int nt = 0; nt < 4; ++nt) {
                    int u = wn * 16 + nt * 4 + tig;
                    float2 v0 = make_float2(acc[mt][nt][0] + cv[mt][0],
                                            acc[mt][nt][1] + cv[mt][0]);
                    float2 v1 = make_float2(acc[mt][nt][2] + cv[mt][1],
                                            acc[mt][nt][3] + cv[mt][1]);
                    *(float2*)(sm2 + OUT_OFF + row * 512       + ((u ^ sw) << 3)) = v0;
                    *(float2*)(sm2 + OUT_OFF + (row + 8) * 512 + ((u ^ sw) << 3)) = v1;
                }
            }
        }
        __syncthreads();
#pragma unroll
        for (int i = 0; i < 4; ++i) {
            int r  = i * 16 + wid;                       // 0..63
            int sw = (r & 3) << 2;
            uint4 v = *(uint4*)(sm2 + OUT_OFF + r * 512 + (((lane << 1) ^ sw) << 3));
            *(uint4*)(out + (size_t)(m0 + r) * NN + n0 + lane * 4) = v;
        }
        __syncthreads();

        // Pass B: rows 64..127 (warps with wm>=2)
        if (wm >= 2) {
#pragma unroll
            for (int mt = 0; mt < 2; ++mt) {
                int row = wm * 32 + mt * 16 + grp;       // 64..127
                int br  = row - 64;                      // br&3 == row&3
                int sw  = (grp & 3) << 2;
#pragma unroll
                for (int nt = 0; nt < 4; ++nt) {
                    int u = wn * 16 + nt * 4 + tig;
                    float2 v0 = make_float2(acc[mt][nt][0] + cv[mt][0],
                                            acc[mt][nt][1] + cv[mt][0]);
                    float2 v1 = make_float2(acc[mt][nt][2] + cv[mt][1],
                                            acc[mt][nt][3] + cv[mt][1]);
                    *(float2*)(sm2 + OUT_OFF + br * 512       + ((u ^ sw) << 3)) = v0;
                    *(float2*)(sm2 + OUT_OFF + (br + 8) * 512 + ((u ^ sw) << 3)) = v1;
                }
            }
        }
        __syncthreads();
#pragma unroll
        for (int i = 0; i < 4; ++i) {
            int br = i * 16 + wid;                       // buffer row 0..63
            int r  = br + 64;                            // out row 64..127
            int sw = (br & 3) << 2;
            uint4 v = *(uint4*)(sm2 + OUT_OFF + br * 512 + (((lane << 1) ^ sw) << 3));
            *(uint4*)(out + (size_t)(m0 + r) * NN + n0 + lane * 4) = v;
        }
        // loop-top syncthreads (after wait_group) orders these reads before
        // the next tile's pass-A STS overwrites the buffer.
    }
}

// ---------------------------------------------------------------------------
extern "C" void kernel_launch(void* const* d_in, const int* in_sizes, int n_in,
                              void* d_out, int out_size) {
    const float* c     = (const float*)d_in[0];   // (2048, 1)
    const float* Q     = (const float*)d_in[1];   // (2048, 96)
    const float* phi   = (const float*)d_in[2];   // (64, 65536)
    const float* theta = (const float*)d_in[3];   // (2080, 32)
    float* out = (float*)d_out;                   // (2048, 65536)

    cudaFuncSetAttribute(quad_kernel, cudaFuncAttributeMaxDynamicSharedMemorySize, SMEM1_BYTES);
    cudaFuncSetAttribute(gemm_kernel, cudaFuncAttributeMaxDynamicSharedMemorySize, SMEM2_BYTES);

    theta_half_kernel<<<130, 256>>>(theta);
    quad_kernel<<<NN / K1_COLS, 512, SMEM1_BYTES>>>(phi);
    gemm_kernel<<<dim3(DD / 128, NN / (128 * NT)), 512, SMEM2_BYTES>>>(c, Q, out);
}

// round 15
// speedup vs baseline: 1.0846x; 1.0846x over previous
#include <cuda_runtime.h>
#include <cuda_bf16.h>
#include <cuda_fp16.h>
#include <math.h>
#include <stdint.h>

// Problem constants
#define NN 65536
#define DD 2048
#define LD 64          // d
#define SS 32          // s
#define KTRI 2080      // d*(d+1)/2
#define KTOT 96        // d + s

// Scratch: z^T n-major fp16, packed pairs: g_z[n*48 + kpair] (uint = half2). 12 MB.
__device__ unsigned g_z[(size_t)NN * 48];
// theta transposed to col-major fp16 pairs: g_theta_h[col*1040 + kpair]. 133 KB.
__device__ unsigned g_theta_h[32 * 1040];

// pack2h(lo, hi): uint with .lo = half(lo), .hi = half(hi)
__device__ __forceinline__ unsigned pack2h(float lo, float hi) {
    unsigned r;
    asm("cvt.rn.f16x2.f32 %0, %1, %2;" : "=r"(r) : "f"(hi), "f"(lo));
    return r;
}

__device__ __forceinline__ void mma_f16(float* c,
                                        unsigned a0, unsigned a1, unsigned a2, unsigned a3,
                                        unsigned b0, unsigned b1) {
    asm volatile(
        "mma.sync.aligned.m16n8k16.row.col.f32.f16.f16.f32 "
        "{%0,%1,%2,%3}, {%4,%5,%6,%7}, {%8,%9}, {%0,%1,%2,%3};"
        : "+f"(c[0]), "+f"(c[1]), "+f"(c[2]), "+f"(c[3])
        : "r"(a0), "r"(a1), "r"(a2), "r"(a3), "r"(b0), "r"(b1));
}

// ---------------------------------------------------------------------------
// Kernel 0: theta (2080 x 32 f32) -> g_theta_h (col-major half2 pairs)
// ---------------------------------------------------------------------------
__global__ void theta_half_kernel(const float* __restrict__ theta) {
    int idx = blockIdx.x * 256 + threadIdx.x;
    if (idx < 32 * 1040) {
        int col = idx / 1040, kp = idx % 1040;
        float lo = theta[(size_t)(2 * kp) * SS + col];
        float hi = theta[(size_t)(2 * kp + 1) * SS + col];
        g_theta_h[idx] = pack2h(lo, hi);
    }
}

// ---------------------------------------------------------------------------
// Kernel 1: quad^T (Ncols x 32) = psi^T (Ncols x 2080) @ theta (2080 x 32)
// R8/R11 shape (256 threads, 8 warps x 32 cols, 2 CTAs/SM) with:
//   - DOUBLE-BUFFERED theta staging via cp.async (barriers 20 -> 11,
//     chunk-boundary LDG latency hidden)
//   - unroll 2 mainloop (cross-iteration ILP; no reg cap)
//   - packed (i|j<<8) ushort pair table (8 index LDS -> 2 per k-step)
// ---------------------------------------------------------------------------
#define K1_COLS 256
#define PHI_STRIDE 264     // floats; conflict-free fragment reads
#define KC 208             // K chunk (2080 = 10 * 208) -> 13 k16-steps
#define TH_STRIDE 108      // uints per theta col (104 pairs + pad)
#define TH_BUF (32 * TH_STRIDE)

#define SMEM1_BYTES ((64 * PHI_STRIDE + 2 * TH_BUF) * 4 + 2 * KTRI)

__device__ __forceinline__ void stage_theta(unsigned* dst, int ch, int tid) {
    for (int idx = tid; idx < 32 * 26; idx += 256) {
        int col = idx / 26, c = idx % 26;
        const unsigned* src = g_theta_h + col * 1040 + ch * 104 + c * 4;
        unsigned sa = (unsigned)__cvta_generic_to_shared(dst + col * TH_STRIDE + c * 4);
        asm volatile("cp.async.cg.shared.global [%0], [%1], 16;" :: "r"(sa), "l"(src));
    }
    asm volatile("cp.async.commit_group;" ::: "memory");
}

__global__ __launch_bounds__(256)
void quad_kernel(const float* __restrict__ phi) {
    extern __shared__ float sm1[];
    float* phi_s     = sm1;                                  // 64 x 264 f32
    unsigned* th0    = (unsigned*)(sm1 + 64 * PHI_STRIDE);   // 2 x (32 x 108) uints
    unsigned short* ps_s = (unsigned short*)(th0 + 2 * TH_BUF);  // 2080 packed pairs

    const int tid  = threadIdx.x;
    const int lane = tid & 31;
    const int wid  = tid >> 5;
    const int tig  = lane & 3;
    const int grp  = lane >> 2;
    const int c0   = blockIdx.x * K1_COLS;

    // Prefetch theta chunk 0 (overlaps with phi staging + transpose)
    stage_theta(th0, 0, tid);

    // Build packed (i | j<<8) table for triu ordering
    for (int k = tid; k < KTRI; k += 256) {
        int gi = (int)(64.5f - sqrtf(64.5f * 64.5f - 2.0f * (float)k));
        gi = max(0, min(63, gi));
        while (gi > 0 && (gi * 64 - (gi * (gi - 1)) / 2) > k) --gi;
        while (gi < 63 && ((gi + 1) * 64 - ((gi + 1) * gi) / 2) <= k) ++gi;
        int base = gi * 64 - (gi * (gi - 1)) / 2;
        ps_s[k] = (unsigned short)(gi | ((gi + (k - base)) << 8));
    }

    // Load phi tile (64 x 256) f32
    for (int idx = tid; idx < 64 * (K1_COLS / 4); idx += 256) {
        int r  = idx / (K1_COLS / 4);
        int c4 = idx % (K1_COLS / 4);
        float4 v = *(const float4*)(phi + (size_t)r * NN + c0 + c4 * 4);
        float* dst = phi_s + r * PHI_STRIDE + c4 * 4;
        dst[0] = v.x; dst[1] = v.y; dst[2] = v.z; dst[3] = v.w;
    }
    __syncthreads();

    // phi rows of z: transpose from smem, each thread owns one n, writes 128B.
    {
        int n = c0 + tid;
#pragma unroll
        for (int kp4 = 0; kp4 < 8; ++kp4) {
            uint4 v;
            unsigned* b = (unsigned*)&v;
#pragma unroll
            for (int j = 0; j < 4; ++j) {
                int kp = kp4 * 4 + j;
                b[j] = pack2h(phi_s[(2 * kp) * PHI_STRIDE + tid],
                              phi_s[(2 * kp + 1) * PHI_STRIDE + tid]);
            }
            *(uint4*)(g_z + (size_t)n * 48 + kp4 * 4) = v;
        }
    }

    float acc[2][4][4];
#pragma unroll
    for (int a = 0; a < 2; a++)
#pragma unroll
        for (int b = 0; b < 4; b++)
#pragma unroll
            for (int q = 0; q < 4; q++) acc[a][b][q] = 0.f;

    const int wcol = wid * 32;

    for (int ch = 0; ch < KTRI / KC; ++ch) {
        const int kb = ch * KC;
        asm volatile("cp.async.wait_group 0;" ::: "memory");
        __syncthreads();   // theta(ch) staged; buf[(ch+1)&1] fully consumed

        if (ch + 1 < KTRI / KC)
            stage_theta(th0 + ((ch + 1) & 1) * TH_BUF, ch + 1, tid);

        const unsigned* th_s = th0 + (ch & 1) * TH_BUF;

#pragma unroll 2
        for (int ks = 0; ks < 13; ++ks) {
            const int kg = kb + ks * 16 + 2 * tig;
            ushort2 pAB = *(const ushort2*)(ps_s + kg);      // pairs kg, kg+1
            ushort2 pCD = *(const ushort2*)(ps_s + kg + 8);  // pairs kg+8, kg+9
            const float* pA = phi_s + (pAB.x & 255) * PHI_STRIDE;
            const float* qA = phi_s + (pAB.x >> 8)  * PHI_STRIDE;
            const float* pB = phi_s + (pAB.y & 255) * PHI_STRIDE;
            const float* qB = phi_s + (pAB.y >> 8)  * PHI_STRIDE;
            const float* pC = phi_s + (pCD.x & 255) * PHI_STRIDE;
            const float* qC = phi_s + (pCD.x >> 8)  * PHI_STRIDE;
            const float* pD = phi_s + (pCD.y & 255) * PHI_STRIDE;
            const float* qD = phi_s + (pCD.y >> 8)  * PHI_STRIDE;

            unsigned bfr[4][2];
#pragma unroll
            for (int nt = 0; nt < 4; ++nt) {
                int col = nt * 8 + grp;
                bfr[nt][0] = th_s[col * TH_STRIDE + ks * 8 + tig];
                bfr[nt][1] = th_s[col * TH_STRIDE + ks * 8 + tig + 4];
            }
#pragma unroll
            for (int mt = 0; mt < 2; ++mt) {
                int col = wcol + mt * 16 + grp;
                unsigned a0 = pack2h(pA[col] * qA[col],         pB[col] * qB[col]);
                unsigned a1 = pack2h(pA[col + 8] * qA[col + 8], pB[col + 8] * qB[col + 8]);
                unsigned a2 = pack2h(pC[col] * qC[col],         pD[col] * qD[col]);
                unsigned a3 = pack2h(pC[col + 8] * qC[col + 8], pD[col + 8] * qD[col + 8]);
#pragma unroll
                for (int nt = 0; nt < 4; ++nt)
                    mma_f16(acc[mt][nt], a0, a1, a2, a3, bfr[nt][0], bfr[nt][1]);
            }
        }
    }

    // Epilogue: quad rows of z (64..95), packed half2
#pragma unroll
    for (int mt = 0; mt < 2; ++mt) {
        int n = c0 + wcol + mt * 16 + grp;
#pragma unroll
        for (int nt = 0; nt < 4; ++nt) {
            g_z[(size_t)n * 48       + 32 + nt * 4 + tig] = pack2h(acc[mt][nt][0], acc[mt][nt][1]);
            g_z[(size_t)(n + 8) * 48 + 32 + nt * 4 + tig] = pack2h(acc[mt][nt][2], acc[mt][nt][3]);
        }
    }
}

// ---------------------------------------------------------------------------
// Kernel 2 (R11 verbatim): out = c + Q @ z, fp16 MMA. Persistent CTA:
// 128 M x NT*128 N. 512 threads / 16 warps (32x32 warp tiles). TWO CTAs/SM:
//   regs <= 64 (launch_bounds(512,2)): A-frags reloaded per k-step from smem.
//   smem 110KB/CTA: Qs 26KB + 2x26KB B bufs + 32KB OUT buffer (2-pass epilogue).
// ---------------------------------------------------------------------------
#define NT 8
#define QSH 52                 // uints (half2 pairs) per Q row
#define BSH 52                 // uints per B row (48 data + pad); 208B, 16B-aligned
#define Q_OFF   0
#define B0_OFF  26624
#define B1_OFF  53248
#define OUT_OFF 79872          // 64 rows x 512B = 32KB
#define SMEM2_BYTES 112640

__device__ __forceinline__ void stage_B(char* Bdst, int n0g, int tid) {
#pragma unroll
    for (int i = 0; i < 3; ++i) {
        int idx = i * 512 + tid;          // 1536 = 128 n x 12 chunks
        int n = idx / 12, q = idx - n * 12;
        const unsigned* src = g_z + (size_t)(n0g + n) * 48 + q * 4;
        unsigned sa = (unsigned)__cvta_generic_to_shared(Bdst + n * (BSH * 4) + q * 16);
        asm volatile("cp.async.cg.shared.global [%0], [%1], 16;" :: "r"(sa), "l"(src));
    }
    asm volatile("cp.async.commit_group;" ::: "memory");
}

__global__ __launch_bounds__(512, 2)
void gemm_kernel(const float* __restrict__ cvec, const float* __restrict__ Q,
                 float* __restrict__ out) {
    extern __shared__ char sm2[];
    unsigned* Qs = (unsigned*)(sm2 + Q_OFF);   // persists across all tiles

    const int tid  = threadIdx.x;
    const int lane = tid & 31;
    const int wid  = tid >> 5;
    const int tig  = lane & 3;
    const int grp  = lane >> 2;
    const int wm   = wid & 3;   // 4 warps along M (32 rows)
    const int wn   = wid >> 2;  // 4 warps along N (32 cols)
    const int m0   = blockIdx.x * 128;         // 16 M-tiles (fast dim -> z L2 reuse)
    const int nb   = blockIdx.y * (128 * NT);  // 64 N-groups

    // Stage Q tile (128 x 96) as half2 pairs
    for (int idx = tid; idx < 128 * 48; idx += 512) {
        int m = idx / 48, hp = idx % 48;
        float2 v = *(const float2*)(Q + (size_t)(m0 + m) * KTOT + hp * 2);
        Qs[m * QSH + hp] = pack2h(v.x, v.y);
    }

    // Prefetch B tile 0
    stage_B(sm2 + B0_OFF, nb, tid);

    float cv[2][2];
#pragma unroll
    for (int mt = 0; mt < 2; ++mt) {
        cv[mt][0] = __ldg(cvec + m0 + wm * 32 + mt * 16 + grp);
        cv[mt][1] = __ldg(cvec + m0 + wm * 32 + mt * 16 + grp + 8);
    }

    __syncthreads();

    for (int t = 0; t < NT; ++t) {
        asm volatile("cp.async.wait_group 0;" ::: "memory");
        __syncthreads();   // B(t) ready; prior OUT-buffer reads complete

        if (t + 1 < NT)
            stage_B(sm2 + ((((t + 1) & 1) == 0) ? B0_OFF : B1_OFF), nb + (t + 1) * 128, tid);

        const unsigned* Bs = (const unsigned*)(sm2 + (((t & 1) == 0) ? B0_OFF : B1_OFF));
        const int n0 = nb + t * 128;

        float acc[2][4][4];
#pragma unroll
        for (int a = 0; a < 2; a++)
#pragma unroll
            for (int b = 0; b < 4; b++)
#pragma unroll
                for (int q = 0; q < 4; q++) acc[a][b][q] = 0.f;

#pragma unroll
        for (int ks = 0; ks < 6; ++ks) {
            // A fragments for this k-step (reloaded; conflict-free banks)
            unsigned afr[2][4];
#pragma unroll
            for (int mt = 0; mt < 2; ++mt) {
                int row = wm * 32 + mt * 16 + grp;
                afr[mt][0] = Qs[row * QSH + ks * 8 + tig];
                afr[mt][1] = Qs[(row + 8) * QSH + ks * 8 + tig];
                afr[mt][2] = Qs[row * QSH + ks * 8 + tig + 4];
                afr[mt][3] = Qs[(row + 8) * QSH + ks * 8 + tig + 4];
            }
#pragma unroll
            for (int nt = 0; nt < 4; ++nt) {
                int coln = wn * 32 + nt * 8 + grp;
                unsigned b0 = Bs[coln * BSH + ks * 8 + tig];
                unsigned b1 = Bs[coln * BSH + ks * 8 + tig + 4];
#pragma unroll
                for (int mt = 0; mt < 2; ++mt)
                    mma_f16(acc[mt][nt], afr[mt][0], afr[mt][1],
                            afr[mt][2], afr[mt][3], b0, b1);
            }
        }

        // ---- 2-pass epilogue through 32KB swizzled OUT buffer ----
        // Pass A: rows 0..63 (warps with wm<2 own them)
        if (wm < 2) {
#pragma unroll
            for (int mt = 0; mt < 2; ++mt) {
                int row = wm * 32 + mt * 16 + grp;       // 0..63; row&3 == grp&3
                int sw  = (grp & 3) << 2;
#pragma unroll
                for (int nt = 0; nt < 4; ++nt) {
                    int u = wn * 16 + nt * 4 + tig;
                    float2 v0 = make_float2(acc[mt][nt][0] + cv[mt][0],
                                            acc[mt][nt][1] + cv[mt][0]);
                    float2 v1 = make_float2(acc[mt][nt][2] + cv[mt][1],
                                            acc[mt][nt][3] + cv[mt][1]);
                    *(float2*)(sm2 + OUT_OFF + row * 512       + ((u ^ sw) << 3)) = v0;
                    *(float2*)(sm2 + OUT_OFF + (row + 8) * 512 + ((u ^ sw) << 3)) = v1;
                }
            }
        }
        __syncthreads();
#pragma unroll
        for (int i = 0; i < 4; ++i) {
            int r  = i * 16 + wid;                       // 0..63
            int sw = (r & 3) << 2;
            uint4 v = *(uint4*)(sm2 + OUT_OFF + r * 512 + (((lane << 1) ^ sw) << 3));
            *(uint4*)(out + (size_t)(m0 + r) * NN + n0 + lane * 4) = v;
        }
        __syncthreads();

        // Pass B: rows 64..127 (warps with wm>=2)
        if (wm >= 2) {
#pragma unroll
            for (int mt = 0; mt < 2; ++mt) {
                int row = wm * 32 + mt * 16 + grp;       // 64..127
                int br  = row - 64;                      // br&3 == row&3
                int sw  = (grp & 3) << 2;
#pragma unroll
                for (int nt = 0; nt < 4; ++nt) {
                    int u = wn * 16 + nt * 4 + tig;
                    float2 v0 = make_float2(acc[mt][nt][0] + cv[mt][0],
                                            acc[mt][nt][1] + cv[mt][0]);
                    float2 v1 = make_float2(acc[mt][nt][2] + cv[mt][1],
                                            acc[mt][nt][3] + cv[mt][1]);
                    *(float2*)(sm2 + OUT_OFF + br * 512       + ((u ^ sw) << 3)) = v0;
                    *(float2*)(sm2 + OUT_OFF + (br + 8) * 512 + ((u ^ sw) << 3)) = v1;
                }
            }
        }
        __syncthreads();
#pragma unroll
        for (int i = 0; i < 4; ++i) {
            int br = i * 16 + wid;                       // buffer row 0..63
            int r  = br + 64;                            // out row 64..127
            int sw = (br & 3) << 2;
            uint4 v = *(uint4*)(sm2 + OUT_OFF + br * 512 + (((lane << 1) ^ sw) << 3));
            *(uint4*)(out + (size_t)(m0 + r) * NN + n0 + lane * 4) = v;
        }
        // loop-top syncthreads (after wait_group) orders these reads before
        // the next tile's pass-A STS overwrites the buffer.
    }
}

// ---------------------------------------------------------------------------
extern "C" void kernel_launch(void* const* d_in, const int* in_sizes, int n_in,
                              void* d_out, int out_size) {
    const float* c     = (const float*)d_in[0];   // (2048, 1)
    const float* Q     = (const float*)d_in[1];   // (2048, 96)
    const float* phi   = (const float*)d_in[2];   // (64, 65536)
    const float* theta = (const float*)d_in[3];   // (2080, 32)
    float* out = (float*)d_out;                   // (2048, 65536)

    cudaFuncSetAttribute(quad_kernel, cudaFuncAttributeMaxDynamicSharedMemorySize, SMEM1_BYTES);
    cudaFuncSetAttribute(gemm_kernel, cudaFuncAttributeMaxDynamicSharedMemorySize, SMEM2_BYTES);

    theta_half_kernel<<<130, 256>>>(theta);
    quad_kernel<<<NN / K1_COLS, 256, SMEM1_BYTES>>>(phi);
    gemm_kernel<<<dim3(DD / 128, NN / (128 * NT)), 512, SMEM2_BYTES>>>(c, Q, out);
}